// round 15
// baseline (speedup 1.0000x reference)
#include <cuda_runtime.h>
#include <math.h>

// EntropyBottleneck — single kernel, single-word producer/consumer handshake.
//
// Structure exploited (verified at runtime per channel):
//   * every m{i} constant-filled -> rank-1 layers
//   * every t{i} == 0            -> tanh gating vanishes
// => lower = alpha*x + beta_l, upper = alpha*x + beta_u per channel.
//
// Block (0,c) produces channel c's params and publishes {alpha, beta_l,
// beta_u, state} in ONE 16B cg-store. Consumers issue their first input
// loads FIRST, then spin on one 16B cg-load (w==0 => not ready) — the
// handshake L2 trip hides under the input DRAM trip. state==2 => full-MLP
// fallback from g_pf (cold, spilled, never taken on this problem's inputs).
//
// EPB=8192: 6144 blocks total — halves per-block fixed costs vs EPB=4096.

__device__ float4 g_abv[256];      // {alpha, beta_l, beta_u, state}
__device__ float  g_pf[256][64];   // full transformed params (fallback only)

// Flat param layout: [0..2]W0 [3..5]B0 [6..8]T0
// layer l in {0,1,2}: base=9+l*15 -> W[0..8], B[9..11], T[12..14]
// [54..56]W4 [57]B4
#define NPARAM 58

__device__ __forceinline__ float softplus_f(float v) {
    if (v > 20.0f) return v;
    if (v < -20.0f) return expf(v);
    return log1pf(expf(v));
}

__device__ __forceinline__ float sigmoid_fast(float x) {
    float e = __expf(-x);
    return __fdividef(1.0f, 1.0f + e);
}

__device__ __forceinline__ float4 ldcg_f4(const float4* p) {
    float4 v;
    asm volatile("ld.global.cg.v4.f32 {%0,%1,%2,%3}, [%4];"
                 : "=f"(v.x), "=f"(v.y), "=f"(v.z), "=f"(v.w) : "l"(p));
    return v;
}

__device__ __forceinline__ void stcg_f4(float4* p, float4 v) {
    asm volatile("st.global.cg.v4.f32 [%0], {%1,%2,%3,%4};"
                 :: "l"(p), "f"(v.x), "f"(v.y), "f"(v.z), "f"(v.w) : "memory");
}

#define EPB 8192   // 256 threads * 8 float4

__global__ __launch_bounds__(256, 6) void eb_kernel(
    const float* __restrict__ in, float* __restrict__ out,
    const float* __restrict__ m0, const float* __restrict__ b0, const float* __restrict__ t0,
    const float* __restrict__ m1, const float* __restrict__ b1, const float* __restrict__ t1,
    const float* __restrict__ m2, const float* __restrict__ b2, const float* __restrict__ t2,
    const float* __restrict__ m3, const float* __restrict__ b3, const float* __restrict__ t3,
    const float* __restrict__ m4, const float* __restrict__ b4,
    int N, long long CN)
{
    const int c   = blockIdx.y;
    const int tid = threadIdx.x;

    const long long base = (long long)c * N;
    const int blk = blockIdx.x * EPB;
    const float* src = in + base;
    const bool interior = (blk + EPB <= N);

    __shared__ float sP[NPARAM];
    __shared__ float sAbv[4];

    float alpha, bl, bu, statef;
    float4 x0, x1;                       // first pair, preloaded pre-handshake

    if (blockIdx.x == 0) {
        // ================= PRODUCER (one block per channel) =================
        int ok = 1;
        if (tid < 3) {
            float v = __ldg(&m0[c * 3 + tid]);
            if (v != __ldg(&m0[c * 3])) ok = 0;
            sP[0 + tid] = softplus_f(v);
            sP[3 + tid] = __ldg(&b0[c * 3 + tid]);
            float tv = __ldg(&t0[c * 3 + tid]);
            if (tv != 0.0f) ok = 0;
            sP[6 + tid] = tanhf(tv);
        } else if (tid < 30) {
            int l = (tid - 3) / 9, j = (tid - 3) % 9;
            const float* m = (l == 0) ? m1 : (l == 1) ? m2 : m3;
            float v = __ldg(&m[c * 9 + j]);
            if (v != __ldg(&m[c * 9])) ok = 0;
            sP[9 + l * 15 + j] = softplus_f(v);
        } else if (tid < 33) {
            int j = tid - 30;
            float v = __ldg(&m4[c * 3 + j]);
            if (v != __ldg(&m4[c * 3])) ok = 0;
            sP[54 + j] = softplus_f(v);
        } else if (tid < 42) {
            int l = (tid - 33) / 3, j = (tid - 33) % 3;
            const float* b = (l == 0) ? b1 : (l == 1) ? b2 : b3;
            const float* t = (l == 0) ? t1 : (l == 1) ? t2 : t3;
            sP[9 + l * 15 + 9 + j] = __ldg(&b[c * 3 + j]);
            float tv = __ldg(&t[c * 3 + j]);
            if (tv != 0.0f) ok = 0;
            sP[9 + l * 15 + 12 + j] = tanhf(tv);
        } else if (tid == 42) {
            sP[57] = __ldg(&b4[c]);
        }
        const int flag = __syncthreads_and(ok);

        if (!flag && tid < NPARAM) g_pf[c][tid] = sP[tid];   // fallback params
        if (!flag) { __syncthreads(); if (tid == 0) __threadfence(); }

        if (tid == 0) {
            float a = sP[0];
            a *= (sP[9]  + sP[10] + sP[11]);
            a *= (sP[24] + sP[25] + sP[26]);
            a *= (sP[39] + sP[40] + sP[41]);
            a *= (sP[54] + sP[55] + sP[56]);

            float y0 = sP[3], y1 = sP[4], y2 = sP[5];
            #pragma unroll
            for (int l = 0; l < 3; l++) {
                const float* W = sP + 9 + l * 15;
                const float* B = W + 9;
                float z0 = W[0] * y0 + W[1] * y1 + W[2] * y2 + B[0];
                float z1 = W[3] * y0 + W[4] * y1 + W[5] * y2 + B[1];
                float z2 = W[6] * y0 + W[7] * y1 + W[8] * y2 + B[2];
                y0 = z0; y1 = z1; y2 = z2;
            }
            float beta = sP[54] * y0 + sP[55] * y1 + sP[56] * y2 + sP[57];
            float hb = 0.5f * a;
            float st = flag ? 1.0f : 2.0f;
            sAbv[0] = a; sAbv[1] = beta - hb; sAbv[2] = beta + hb; sAbv[3] = st;
            // single-16B-store publication: payload + flag in one sector
            stcg_f4(&g_abv[c], make_float4(a, beta - hb, beta + hb, st));
        }
        __syncthreads();
        alpha = sAbv[0]; bl = sAbv[1]; bu = sAbv[2]; statef = sAbv[3];
        if (interior) {
            x0 = __ldcs((const float4*)(src + blk + tid * 4));
            x1 = __ldcs((const float4*)(src + blk + tid * 4 + 1024));
        }
    } else {
        // ===== CONSUMER: input loads FIRST, then one-word handshake =========
        if (interior) {
            x0 = __ldcs((const float4*)(src + blk + tid * 4));
            x1 = __ldcs((const float4*)(src + blk + tid * 4 + 1024));
        }
        float4 v = ldcg_f4(&g_abv[c]);
        while (v.w == 0.0f) { __nanosleep(64); v = ldcg_f4(&g_abv[c]); }
        alpha = v.x; bl = v.y; bu = v.z; statef = v.w;
    }

    float* lik = out + base;
    float* low = out + CN + base;
    float* upp = out + 2 * CN + base;

    if (statef == 1.0f) {
        // ---- HOT stream: 8 float4/thread, paired-load ILP ------------------
        if (interior) {
            #pragma unroll
            for (int i = 0; i < 4; i++) {
                const int a0 = blk + i * 2048 + tid * 4;
                const int a1 = a0 + 1024;
                if (i) {                  // later pairs loaded in-loop
                    x0 = __ldcs((const float4*)(src + a0));
                    x1 = __ldcs((const float4*)(src + a1));
                }

                float4 l0, u0, k0;
                l0.x = fmaf(alpha, x0.x, bl); u0.x = fmaf(alpha, x0.x, bu);
                l0.y = fmaf(alpha, x0.y, bl); u0.y = fmaf(alpha, x0.y, bu);
                l0.z = fmaf(alpha, x0.z, bl); u0.z = fmaf(alpha, x0.z, bu);
                l0.w = fmaf(alpha, x0.w, bl); u0.w = fmaf(alpha, x0.w, bu);
                k0.x = sigmoid_fast(u0.x) - sigmoid_fast(l0.x);
                k0.y = sigmoid_fast(u0.y) - sigmoid_fast(l0.y);
                k0.z = sigmoid_fast(u0.z) - sigmoid_fast(l0.z);
                k0.w = sigmoid_fast(u0.w) - sigmoid_fast(l0.w);
                __stcs((float4*)(lik + a0), k0);
                __stcs((float4*)(low + a0), l0);
                __stcs((float4*)(upp + a0), u0);

                float4 l1, u1, k1;
                l1.x = fmaf(alpha, x1.x, bl); u1.x = fmaf(alpha, x1.x, bu);
                l1.y = fmaf(alpha, x1.y, bl); u1.y = fmaf(alpha, x1.y, bu);
                l1.z = fmaf(alpha, x1.z, bl); u1.z = fmaf(alpha, x1.z, bu);
                l1.w = fmaf(alpha, x1.w, bl); u1.w = fmaf(alpha, x1.w, bu);
                k1.x = sigmoid_fast(u1.x) - sigmoid_fast(l1.x);
                k1.y = sigmoid_fast(u1.y) - sigmoid_fast(l1.y);
                k1.z = sigmoid_fast(u1.z) - sigmoid_fast(l1.z);
                k1.w = sigmoid_fast(u1.w) - sigmoid_fast(l1.w);
                __stcs((float4*)(lik + a1), k1);
                __stcs((float4*)(low + a1), l1);
                __stcs((float4*)(upp + a1), u1);
            }
        } else {
            for (int i = 0; i < 8; i++) {
                int s = blk + i * 1024 + tid * 4;
                int lim = min(s + 4, N);
                for (int q = s; q < lim; q++) {
                    float x = src[q];
                    float l = fmaf(alpha, x, bl);
                    float u = fmaf(alpha, x, bu);
                    lik[q] = sigmoid_fast(u) - sigmoid_fast(l);
                    low[q] = l;
                    upp[q] = u;
                }
            }
        }
    } else {
        // ---- COLD safety net: full MLP for this slice (never taken) --------
        if (blockIdx.x != 0) {            // consumers fetch published params
            if (tid < NPARAM) sP[tid] = __ldcg(&g_pf[c][tid]);
            __syncthreads();
        }
        const int end = min(blk + EPB, N);
        for (int e = blk + tid; e < end; e += 256) {
            float x = src[e];
            float r2[2];
            #pragma unroll
            for (int s = 0; s < 2; s++) {
                float xi = x + (s ? 0.5f : -0.5f);
                float y0 = fmaf(sP[0], xi, sP[3]);
                float y1 = fmaf(sP[1], xi, sP[4]);
                float y2 = fmaf(sP[2], xi, sP[5]);
                y0 = fmaf(sP[6], tanhf(y0), y0);
                y1 = fmaf(sP[7], tanhf(y1), y1);
                y2 = fmaf(sP[8], tanhf(y2), y2);
                #pragma unroll
                for (int l = 0; l < 3; l++) {
                    const float* W = sP + 9 + l * 15;
                    const float* B = W + 9;
                    const float* T = W + 12;
                    float z0 = W[0] * y0 + W[1] * y1 + W[2] * y2 + B[0];
                    float z1 = W[3] * y0 + W[4] * y1 + W[5] * y2 + B[1];
                    float z2 = W[6] * y0 + W[7] * y1 + W[8] * y2 + B[2];
                    y0 = fmaf(T[0], tanhf(z0), z0);
                    y1 = fmaf(T[1], tanhf(z1), z1);
                    y2 = fmaf(T[2], tanhf(z2), z2);
                }
                r2[s] = sP[54] * y0 + sP[55] * y1 + sP[56] * y2 + sP[57];
            }
            lik[e] = 1.0f / (1.0f + expf(-r2[1])) - 1.0f / (1.0f + expf(-r2[0]));
            low[e] = r2[0];
            upp[e] = r2[1];
        }
    }
}

// ---------------------------------------------------------------------------
// Host launcher — single kernel launch.
// ---------------------------------------------------------------------------
extern "C" void kernel_launch(void* const* d_in, const int* in_sizes, int n_in,
                              void* d_out, int out_size)
{
    // Input-order detection.
    // Order A (dict order): inputs, m0,b0,t0, m1,b1,t1, m2,b2,t2, m3,b3,t3, m4,b4
    // Order B (signature):  inputs, m0..m4, b0..b4, t0..t3
    int im[5], ib[5], it[4];
    if (n_in >= 15 && in_sizes[2] == in_sizes[1]) {
        im[0] = 1;  ib[0] = 2;  it[0] = 3;
        im[1] = 4;  ib[1] = 5;  it[1] = 6;
        im[2] = 7;  ib[2] = 8;  it[2] = 9;
        im[3] = 10; ib[3] = 11; it[3] = 12;
        im[4] = 13; ib[4] = 14;
    } else {
        im[0] = 1; im[1] = 2; im[2] = 3; im[3] = 4; im[4] = 5;
        ib[0] = 6; ib[1] = 7; ib[2] = 8; ib[3] = 9; ib[4] = 10;
        it[0] = 11; it[1] = 12; it[2] = 13; it[3] = 14;
    }

    const float* in = (const float*)d_in[0];
    float* out = (float*)d_out;

    int C = in_sizes[ib[4]];          // b4 is (C,1,1)
    if (C <= 0 || C > 256) C = 192;
    int N = in_sizes[0] / C;
    long long CN = (long long)C * N;

    dim3 grid((N + EPB - 1) / EPB, C);
    eb_kernel<<<grid, 256>>>(
        in, out,
        (const float*)d_in[im[0]], (const float*)d_in[ib[0]], (const float*)d_in[it[0]],
        (const float*)d_in[im[1]], (const float*)d_in[ib[1]], (const float*)d_in[it[1]],
        (const float*)d_in[im[2]], (const float*)d_in[ib[2]], (const float*)d_in[it[2]],
        (const float*)d_in[im[3]], (const float*)d_in[ib[3]], (const float*)d_in[it[3]],
        (const float*)d_in[im[4]], (const float*)d_in[ib[4]],
        N, CN);
}

// round 16
// speedup vs baseline: 1.0251x; 1.0251x over previous
#include <cuda_runtime.h>
#include <math.h>

// EntropyBottleneck — single kernel, single-word producer/consumer handshake.
// (Converged configuration — EPB=4096; coarser tiles measured slower.)
//
// Structure exploited (verified at runtime per channel):
//   * every m{i} constant-filled -> rank-1 layers
//   * every t{i} == 0            -> tanh gating vanishes
// => lower = alpha*x + beta_l, upper = alpha*x + beta_u per channel.
//
// Block (0,c) produces channel c's params and publishes {alpha, beta_l,
// beta_u, state} in ONE 16B cg-store. Consumers issue their first input
// loads FIRST, then spin on one 16B cg-load (w==0 => not ready) — the
// handshake L2 trip hides under the input DRAM trip. state==2 => full-MLP
// fallback from g_pf (cold, spilled, never taken on this problem's inputs).

__device__ float4 g_abv[256];      // {alpha, beta_l, beta_u, state}
__device__ float  g_pf[256][64];   // full transformed params (fallback only)

// Flat param layout: [0..2]W0 [3..5]B0 [6..8]T0
// layer l in {0,1,2}: base=9+l*15 -> W[0..8], B[9..11], T[12..14]
// [54..56]W4 [57]B4
#define NPARAM 58

__device__ __forceinline__ float softplus_f(float v) {
    if (v > 20.0f) return v;
    if (v < -20.0f) return expf(v);
    return log1pf(expf(v));
}

__device__ __forceinline__ float sigmoid_fast(float x) {
    float e = __expf(-x);
    return __fdividef(1.0f, 1.0f + e);
}

__device__ __forceinline__ float4 ldcg_f4(const float4* p) {
    float4 v;
    asm volatile("ld.global.cg.v4.f32 {%0,%1,%2,%3}, [%4];"
                 : "=f"(v.x), "=f"(v.y), "=f"(v.z), "=f"(v.w) : "l"(p));
    return v;
}

__device__ __forceinline__ void stcg_f4(float4* p, float4 v) {
    asm volatile("st.global.cg.v4.f32 [%0], {%1,%2,%3,%4};"
                 :: "l"(p), "f"(v.x), "f"(v.y), "f"(v.z), "f"(v.w) : "memory");
}

#define EPB 4096   // 256 threads * 4 float4

__global__ __launch_bounds__(256, 6) void eb_kernel(
    const float* __restrict__ in, float* __restrict__ out,
    const float* __restrict__ m0, const float* __restrict__ b0, const float* __restrict__ t0,
    const float* __restrict__ m1, const float* __restrict__ b1, const float* __restrict__ t1,
    const float* __restrict__ m2, const float* __restrict__ b2, const float* __restrict__ t2,
    const float* __restrict__ m3, const float* __restrict__ b3, const float* __restrict__ t3,
    const float* __restrict__ m4, const float* __restrict__ b4,
    int N, long long CN)
{
    const int c   = blockIdx.y;
    const int tid = threadIdx.x;

    const long long base = (long long)c * N;
    const int blk = blockIdx.x * EPB;
    const float* src = in + base;
    const bool interior = (blk + EPB <= N);

    __shared__ float sP[NPARAM];
    __shared__ float sAbv[4];

    float alpha, bl, bu, statef;
    float4 x0, x1;                       // first pair, preloaded pre-handshake

    if (blockIdx.x == 0) {
        // ================= PRODUCER (one block per channel) =================
        int ok = 1;
        if (tid < 3) {
            float v = __ldg(&m0[c * 3 + tid]);
            if (v != __ldg(&m0[c * 3])) ok = 0;
            sP[0 + tid] = softplus_f(v);
            sP[3 + tid] = __ldg(&b0[c * 3 + tid]);
            float tv = __ldg(&t0[c * 3 + tid]);
            if (tv != 0.0f) ok = 0;
            sP[6 + tid] = tanhf(tv);
        } else if (tid < 30) {
            int l = (tid - 3) / 9, j = (tid - 3) % 9;
            const float* m = (l == 0) ? m1 : (l == 1) ? m2 : m3;
            float v = __ldg(&m[c * 9 + j]);
            if (v != __ldg(&m[c * 9])) ok = 0;
            sP[9 + l * 15 + j] = softplus_f(v);
        } else if (tid < 33) {
            int j = tid - 30;
            float v = __ldg(&m4[c * 3 + j]);
            if (v != __ldg(&m4[c * 3])) ok = 0;
            sP[54 + j] = softplus_f(v);
        } else if (tid < 42) {
            int l = (tid - 33) / 3, j = (tid - 33) % 3;
            const float* b = (l == 0) ? b1 : (l == 1) ? b2 : b3;
            const float* t = (l == 0) ? t1 : (l == 1) ? t2 : t3;
            sP[9 + l * 15 + 9 + j] = __ldg(&b[c * 3 + j]);
            float tv = __ldg(&t[c * 3 + j]);
            if (tv != 0.0f) ok = 0;
            sP[9 + l * 15 + 12 + j] = tanhf(tv);
        } else if (tid == 42) {
            sP[57] = __ldg(&b4[c]);
        }
        const int flag = __syncthreads_and(ok);

        if (!flag && tid < NPARAM) g_pf[c][tid] = sP[tid];   // fallback params
        if (!flag) { __syncthreads(); if (tid == 0) __threadfence(); }

        if (tid == 0) {
            float a = sP[0];
            a *= (sP[9]  + sP[10] + sP[11]);
            a *= (sP[24] + sP[25] + sP[26]);
            a *= (sP[39] + sP[40] + sP[41]);
            a *= (sP[54] + sP[55] + sP[56]);

            float y0 = sP[3], y1 = sP[4], y2 = sP[5];
            #pragma unroll
            for (int l = 0; l < 3; l++) {
                const float* W = sP + 9 + l * 15;
                const float* B = W + 9;
                float z0 = W[0] * y0 + W[1] * y1 + W[2] * y2 + B[0];
                float z1 = W[3] * y0 + W[4] * y1 + W[5] * y2 + B[1];
                float z2 = W[6] * y0 + W[7] * y1 + W[8] * y2 + B[2];
                y0 = z0; y1 = z1; y2 = z2;
            }
            float beta = sP[54] * y0 + sP[55] * y1 + sP[56] * y2 + sP[57];
            float hb = 0.5f * a;
            float st = flag ? 1.0f : 2.0f;
            sAbv[0] = a; sAbv[1] = beta - hb; sAbv[2] = beta + hb; sAbv[3] = st;
            // single-16B-store publication: payload + flag in one sector
            stcg_f4(&g_abv[c], make_float4(a, beta - hb, beta + hb, st));
        }
        __syncthreads();
        alpha = sAbv[0]; bl = sAbv[1]; bu = sAbv[2]; statef = sAbv[3];
        if (interior) {
            x0 = __ldcs((const float4*)(src + blk + tid * 4));
            x1 = __ldcs((const float4*)(src + blk + tid * 4 + 1024));
        }
    } else {
        // ===== CONSUMER: input loads FIRST, then one-word handshake =========
        if (interior) {
            x0 = __ldcs((const float4*)(src + blk + tid * 4));
            x1 = __ldcs((const float4*)(src + blk + tid * 4 + 1024));
        }
        float4 v = ldcg_f4(&g_abv[c]);
        while (v.w == 0.0f) { __nanosleep(64); v = ldcg_f4(&g_abv[c]); }
        alpha = v.x; bl = v.y; bu = v.z; statef = v.w;
    }

    float* lik = out + base;
    float* low = out + CN + base;
    float* upp = out + 2 * CN + base;

    if (statef == 1.0f) {
        // ---- HOT stream: 4 float4/thread, paired-load ILP ------------------
        if (interior) {
            #pragma unroll
            for (int i = 0; i < 2; i++) {
                const int a0 = blk + i * 2048 + tid * 4;
                const int a1 = a0 + 1024;
                if (i) {                  // second pair loaded in-loop
                    x0 = __ldcs((const float4*)(src + a0));
                    x1 = __ldcs((const float4*)(src + a1));
                }

                float4 l0, u0, k0;
                l0.x = fmaf(alpha, x0.x, bl); u0.x = fmaf(alpha, x0.x, bu);
                l0.y = fmaf(alpha, x0.y, bl); u0.y = fmaf(alpha, x0.y, bu);
                l0.z = fmaf(alpha, x0.z, bl); u0.z = fmaf(alpha, x0.z, bu);
                l0.w = fmaf(alpha, x0.w, bl); u0.w = fmaf(alpha, x0.w, bu);
                k0.x = sigmoid_fast(u0.x) - sigmoid_fast(l0.x);
                k0.y = sigmoid_fast(u0.y) - sigmoid_fast(l0.y);
                k0.z = sigmoid_fast(u0.z) - sigmoid_fast(l0.z);
                k0.w = sigmoid_fast(u0.w) - sigmoid_fast(l0.w);
                __stcs((float4*)(lik + a0), k0);
                __stcs((float4*)(low + a0), l0);
                __stcs((float4*)(upp + a0), u0);

                float4 l1, u1, k1;
                l1.x = fmaf(alpha, x1.x, bl); u1.x = fmaf(alpha, x1.x, bu);
                l1.y = fmaf(alpha, x1.y, bl); u1.y = fmaf(alpha, x1.y, bu);
                l1.z = fmaf(alpha, x1.z, bl); u1.z = fmaf(alpha, x1.z, bu);
                l1.w = fmaf(alpha, x1.w, bl); u1.w = fmaf(alpha, x1.w, bu);
                k1.x = sigmoid_fast(u1.x) - sigmoid_fast(l1.x);
                k1.y = sigmoid_fast(u1.y) - sigmoid_fast(l1.y);
                k1.z = sigmoid_fast(u1.z) - sigmoid_fast(l1.z);
                k1.w = sigmoid_fast(u1.w) - sigmoid_fast(l1.w);
                __stcs((float4*)(lik + a1), k1);
                __stcs((float4*)(low + a1), l1);
                __stcs((float4*)(upp + a1), u1);
            }
        } else {
            for (int i = 0; i < 4; i++) {
                int s = blk + i * 1024 + tid * 4;
                int lim = min(s + 4, N);
                for (int q = s; q < lim; q++) {
                    float x = src[q];
                    float l = fmaf(alpha, x, bl);
                    float u = fmaf(alpha, x, bu);
                    lik[q] = sigmoid_fast(u) - sigmoid_fast(l);
                    low[q] = l;
                    upp[q] = u;
                }
            }
        }
    } else {
        // ---- COLD safety net: full MLP for this slice (never taken) --------
        if (blockIdx.x != 0) {            // consumers fetch published params
            if (tid < NPARAM) sP[tid] = __ldcg(&g_pf[c][tid]);
            __syncthreads();
        }
        const int end = min(blk + EPB, N);
        for (int e = blk + tid; e < end; e += 256) {
            float x = src[e];
            float r2[2];
            #pragma unroll
            for (int s = 0; s < 2; s++) {
                float xi = x + (s ? 0.5f : -0.5f);
                float y0 = fmaf(sP[0], xi, sP[3]);
                float y1 = fmaf(sP[1], xi, sP[4]);
                float y2 = fmaf(sP[2], xi, sP[5]);
                y0 = fmaf(sP[6], tanhf(y0), y0);
                y1 = fmaf(sP[7], tanhf(y1), y1);
                y2 = fmaf(sP[8], tanhf(y2), y2);
                #pragma unroll
                for (int l = 0; l < 3; l++) {
                    const float* W = sP + 9 + l * 15;
                    const float* B = W + 9;
                    const float* T = W + 12;
                    float z0 = W[0] * y0 + W[1] * y1 + W[2] * y2 + B[0];
                    float z1 = W[3] * y0 + W[4] * y1 + W[5] * y2 + B[1];
                    float z2 = W[6] * y0 + W[7] * y1 + W[8] * y2 + B[2];
                    y0 = fmaf(T[0], tanhf(z0), z0);
                    y1 = fmaf(T[1], tanhf(z1), z1);
                    y2 = fmaf(T[2], tanhf(z2), z2);
                }
                r2[s] = sP[54] * y0 + sP[55] * y1 + sP[56] * y2 + sP[57];
            }
            lik[e] = 1.0f / (1.0f + expf(-r2[1])) - 1.0f / (1.0f + expf(-r2[0]));
            low[e] = r2[0];
            upp[e] = r2[1];
        }
    }
}

// ---------------------------------------------------------------------------
// Host launcher — single kernel launch.
// ---------------------------------------------------------------------------
extern "C" void kernel_launch(void* const* d_in, const int* in_sizes, int n_in,
                              void* d_out, int out_size)
{
    // Input-order detection.
    // Order A (dict order): inputs, m0,b0,t0, m1,b1,t1, m2,b2,t2, m3,b3,t3, m4,b4
    // Order B (signature):  inputs, m0..m4, b0..b4, t0..t3
    int im[5], ib[5], it[4];
    if (n_in >= 15 && in_sizes[2] == in_sizes[1]) {
        im[0] = 1;  ib[0] = 2;  it[0] = 3;
        im[1] = 4;  ib[1] = 5;  it[1] = 6;
        im[2] = 7;  ib[2] = 8;  it[2] = 9;
        im[3] = 10; ib[3] = 11; it[3] = 12;
        im[4] = 13; ib[4] = 14;
    } else {
        im[0] = 1; im[1] = 2; im[2] = 3; im[3] = 4; im[4] = 5;
        ib[0] = 6; ib[1] = 7; ib[2] = 8; ib[3] = 9; ib[4] = 10;
        it[0] = 11; it[1] = 12; it[2] = 13; it[3] = 14;
    }

    const float* in = (const float*)d_in[0];
    float* out = (float*)d_out;

    int C = in_sizes[ib[4]];          // b4 is (C,1,1)
    if (C <= 0 || C > 256) C = 192;
    int N = in_sizes[0] / C;
    long long CN = (long long)C * N;

    dim3 grid((N + EPB - 1) / EPB, C);
    eb_kernel<<<grid, 256>>>(
        in, out,
        (const float*)d_in[im[0]], (const float*)d_in[ib[0]], (const float*)d_in[it[0]],
        (const float*)d_in[im[1]], (const float*)d_in[ib[1]], (const float*)d_in[it[1]],
        (const float*)d_in[im[2]], (const float*)d_in[ib[2]], (const float*)d_in[it[2]],
        (const float*)d_in[im[3]], (const float*)d_in[ib[3]], (const float*)d_in[it[3]],
        (const float*)d_in[im[4]], (const float*)d_in[ib[4]],
        N, CN);
}

// round 17
// speedup vs baseline: 1.0451x; 1.0195x over previous
#include <cuda_runtime.h>
#include <math.h>

// EntropyBottleneck — single kernel, single-word handshake, straight-line body.
// EPB=2048: every thread's ENTIRE workload (2 float4) is preloaded before the
// handshake — zero post-handshake input latency; finer blocks shrink the
// tail-wave imbalance.
//
// Structure exploited (verified at runtime per channel):
//   * every m{i} constant-filled -> rank-1 layers
//   * every t{i} == 0            -> tanh gating vanishes
// => lower = alpha*x + beta_l, upper = alpha*x + beta_u per channel.
//
// Block (0,c) produces channel c's params and publishes {alpha, beta_l,
// beta_u, state} in ONE 16B cg-store. Consumers issue both input loads
// FIRST, then spin on one 16B cg-load (w==0 => not ready). state==2 =>
// full-MLP fallback from g_pf (cold, spilled, never taken on this problem).

__device__ float4 g_abv[256];      // {alpha, beta_l, beta_u, state}
__device__ float  g_pf[256][64];   // full transformed params (fallback only)

// Flat param layout: [0..2]W0 [3..5]B0 [6..8]T0
// layer l in {0,1,2}: base=9+l*15 -> W[0..8], B[9..11], T[12..14]
// [54..56]W4 [57]B4
#define NPARAM 58

__device__ __forceinline__ float softplus_f(float v) {
    if (v > 20.0f) return v;
    if (v < -20.0f) return expf(v);
    return log1pf(expf(v));
}

__device__ __forceinline__ float sigmoid_fast(float x) {
    float e = __expf(-x);
    return __fdividef(1.0f, 1.0f + e);
}

__device__ __forceinline__ float4 ldcg_f4(const float4* p) {
    float4 v;
    asm volatile("ld.global.cg.v4.f32 {%0,%1,%2,%3}, [%4];"
                 : "=f"(v.x), "=f"(v.y), "=f"(v.z), "=f"(v.w) : "l"(p));
    return v;
}

__device__ __forceinline__ void stcg_f4(float4* p, float4 v) {
    asm volatile("st.global.cg.v4.f32 [%0], {%1,%2,%3,%4};"
                 :: "l"(p), "f"(v.x), "f"(v.y), "f"(v.z), "f"(v.w) : "memory");
}

#define EPB 2048   // 256 threads * 2 float4 — whole block preloaded

__global__ __launch_bounds__(256, 6) void eb_kernel(
    const float* __restrict__ in, float* __restrict__ out,
    const float* __restrict__ m0, const float* __restrict__ b0, const float* __restrict__ t0,
    const float* __restrict__ m1, const float* __restrict__ b1, const float* __restrict__ t1,
    const float* __restrict__ m2, const float* __restrict__ b2, const float* __restrict__ t2,
    const float* __restrict__ m3, const float* __restrict__ b3, const float* __restrict__ t3,
    const float* __restrict__ m4, const float* __restrict__ b4,
    int N, long long CN)
{
    const int c   = blockIdx.y;
    const int tid = threadIdx.x;

    const long long base = (long long)c * N;
    const int blk = blockIdx.x * EPB;
    const float* src = in + base;
    const bool interior = (blk + EPB <= N);

    __shared__ float sP[NPARAM];
    __shared__ float sAbv[4];

    float alpha, bl, bu, statef;
    float4 x0, x1;                       // ENTIRE workload, preloaded

    if (blockIdx.x == 0) {
        // ================= PRODUCER (one block per channel) =================
        int ok = 1;
        if (tid < 3) {
            float v = __ldg(&m0[c * 3 + tid]);
            if (v != __ldg(&m0[c * 3])) ok = 0;
            sP[0 + tid] = softplus_f(v);
            sP[3 + tid] = __ldg(&b0[c * 3 + tid]);
            float tv = __ldg(&t0[c * 3 + tid]);
            if (tv != 0.0f) ok = 0;
            sP[6 + tid] = tanhf(tv);
        } else if (tid < 30) {
            int l = (tid - 3) / 9, j = (tid - 3) % 9;
            const float* m = (l == 0) ? m1 : (l == 1) ? m2 : m3;
            float v = __ldg(&m[c * 9 + j]);
            if (v != __ldg(&m[c * 9])) ok = 0;
            sP[9 + l * 15 + j] = softplus_f(v);
        } else if (tid < 33) {
            int j = tid - 30;
            float v = __ldg(&m4[c * 3 + j]);
            if (v != __ldg(&m4[c * 3])) ok = 0;
            sP[54 + j] = softplus_f(v);
        } else if (tid < 42) {
            int l = (tid - 33) / 3, j = (tid - 33) % 3;
            const float* b = (l == 0) ? b1 : (l == 1) ? b2 : b3;
            const float* t = (l == 0) ? t1 : (l == 1) ? t2 : t3;
            sP[9 + l * 15 + 9 + j] = __ldg(&b[c * 3 + j]);
            float tv = __ldg(&t[c * 3 + j]);
            if (tv != 0.0f) ok = 0;
            sP[9 + l * 15 + 12 + j] = tanhf(tv);
        } else if (tid == 42) {
            sP[57] = __ldg(&b4[c]);
        }
        const int flag = __syncthreads_and(ok);

        if (!flag && tid < NPARAM) g_pf[c][tid] = sP[tid];   // fallback params
        if (!flag) { __syncthreads(); if (tid == 0) __threadfence(); }

        if (tid == 0) {
            float a = sP[0];
            a *= (sP[9]  + sP[10] + sP[11]);
            a *= (sP[24] + sP[25] + sP[26]);
            a *= (sP[39] + sP[40] + sP[41]);
            a *= (sP[54] + sP[55] + sP[56]);

            float y0 = sP[3], y1 = sP[4], y2 = sP[5];
            #pragma unroll
            for (int l = 0; l < 3; l++) {
                const float* W = sP + 9 + l * 15;
                const float* B = W + 9;
                float z0 = W[0] * y0 + W[1] * y1 + W[2] * y2 + B[0];
                float z1 = W[3] * y0 + W[4] * y1 + W[5] * y2 + B[1];
                float z2 = W[6] * y0 + W[7] * y1 + W[8] * y2 + B[2];
                y0 = z0; y1 = z1; y2 = z2;
            }
            float beta = sP[54] * y0 + sP[55] * y1 + sP[56] * y2 + sP[57];
            float hb = 0.5f * a;
            float st = flag ? 1.0f : 2.0f;
            sAbv[0] = a; sAbv[1] = beta - hb; sAbv[2] = beta + hb; sAbv[3] = st;
            // single-16B-store publication: payload + flag in one sector
            stcg_f4(&g_abv[c], make_float4(a, beta - hb, beta + hb, st));
        }
        __syncthreads();
        alpha = sAbv[0]; bl = sAbv[1]; bu = sAbv[2]; statef = sAbv[3];
        if (interior) {
            x0 = __ldcs((const float4*)(src + blk + tid * 4));
            x1 = __ldcs((const float4*)(src + blk + tid * 4 + 1024));
        }
    } else {
        // ===== CONSUMER: ALL input loads first, then one-word handshake =====
        if (interior) {
            x0 = __ldcs((const float4*)(src + blk + tid * 4));
            x1 = __ldcs((const float4*)(src + blk + tid * 4 + 1024));
        }
        float4 v = ldcg_f4(&g_abv[c]);
        while (v.w == 0.0f) { __nanosleep(64); v = ldcg_f4(&g_abv[c]); }
        alpha = v.x; bl = v.y; bu = v.z; statef = v.w;
    }

    float* lik = out + base;
    float* low = out + CN + base;
    float* upp = out + 2 * CN + base;

    if (statef == 1.0f) {
        // ---- HOT: straight-line, zero post-handshake input latency ---------
        if (interior) {
            const int a0 = blk + tid * 4;
            const int a1 = a0 + 1024;

            float4 l0, u0, k0;
            l0.x = fmaf(alpha, x0.x, bl); u0.x = fmaf(alpha, x0.x, bu);
            l0.y = fmaf(alpha, x0.y, bl); u0.y = fmaf(alpha, x0.y, bu);
            l0.z = fmaf(alpha, x0.z, bl); u0.z = fmaf(alpha, x0.z, bu);
            l0.w = fmaf(alpha, x0.w, bl); u0.w = fmaf(alpha, x0.w, bu);
            k0.x = sigmoid_fast(u0.x) - sigmoid_fast(l0.x);
            k0.y = sigmoid_fast(u0.y) - sigmoid_fast(l0.y);
            k0.z = sigmoid_fast(u0.z) - sigmoid_fast(l0.z);
            k0.w = sigmoid_fast(u0.w) - sigmoid_fast(l0.w);
            __stcs((float4*)(lik + a0), k0);
            __stcs((float4*)(low + a0), l0);
            __stcs((float4*)(upp + a0), u0);

            float4 l1, u1, k1;
            l1.x = fmaf(alpha, x1.x, bl); u1.x = fmaf(alpha, x1.x, bu);
            l1.y = fmaf(alpha, x1.y, bl); u1.y = fmaf(alpha, x1.y, bu);
            l1.z = fmaf(alpha, x1.z, bl); u1.z = fmaf(alpha, x1.z, bu);
            l1.w = fmaf(alpha, x1.w, bl); u1.w = fmaf(alpha, x1.w, bu);
            k1.x = sigmoid_fast(u1.x) - sigmoid_fast(l1.x);
            k1.y = sigmoid_fast(u1.y) - sigmoid_fast(l1.y);
            k1.z = sigmoid_fast(u1.z) - sigmoid_fast(l1.z);
            k1.w = sigmoid_fast(u1.w) - sigmoid_fast(l1.w);
            __stcs((float4*)(lik + a1), k1);
            __stcs((float4*)(low + a1), l1);
            __stcs((float4*)(upp + a1), u1);
        } else {
            for (int i = 0; i < 2; i++) {
                int s = blk + i * 1024 + tid * 4;
                int lim = min(s + 4, N);
                for (int q = s; q < lim; q++) {
                    float x = src[q];
                    float l = fmaf(alpha, x, bl);
                    float u = fmaf(alpha, x, bu);
                    lik[q] = sigmoid_fast(u) - sigmoid_fast(l);
                    low[q] = l;
                    upp[q] = u;
                }
            }
        }
    } else {
        // ---- COLD safety net: full MLP for this slice (never taken) --------
        if (blockIdx.x != 0) {            // consumers fetch published params
            if (tid < NPARAM) sP[tid] = __ldcg(&g_pf[c][tid]);
            __syncthreads();
        }
        const int end = min(blk + EPB, N);
        for (int e = blk + tid; e < end; e += 256) {
            float x = src[e];
            float r2[2];
            #pragma unroll
            for (int s = 0; s < 2; s++) {
                float xi = x + (s ? 0.5f : -0.5f);
                float y0 = fmaf(sP[0], xi, sP[3]);
                float y1 = fmaf(sP[1], xi, sP[4]);
                float y2 = fmaf(sP[2], xi, sP[5]);
                y0 = fmaf(sP[6], tanhf(y0), y0);
                y1 = fmaf(sP[7], tanhf(y1), y1);
                y2 = fmaf(sP[8], tanhf(y2), y2);
                #pragma unroll
                for (int l = 0; l < 3; l++) {
                    const float* W = sP + 9 + l * 15;
                    const float* B = W + 9;
                    const float* T = W + 12;
                    float z0 = W[0] * y0 + W[1] * y1 + W[2] * y2 + B[0];
                    float z1 = W[3] * y0 + W[4] * y1 + W[5] * y2 + B[1];
                    float z2 = W[6] * y0 + W[7] * y1 + W[8] * y2 + B[2];
                    y0 = fmaf(T[0], tanhf(z0), z0);
                    y1 = fmaf(T[1], tanhf(z1), z1);
                    y2 = fmaf(T[2], tanhf(z2), z2);
                }
                r2[s] = sP[54] * y0 + sP[55] * y1 + sP[56] * y2 + sP[57];
            }
            lik[e] = 1.0f / (1.0f + expf(-r2[1])) - 1.0f / (1.0f + expf(-r2[0]));
            low[e] = r2[0];
            upp[e] = r2[1];
        }
    }
}

// ---------------------------------------------------------------------------
// Host launcher — single kernel launch.
// ---------------------------------------------------------------------------
extern "C" void kernel_launch(void* const* d_in, const int* in_sizes, int n_in,
                              void* d_out, int out_size)
{
    // Input-order detection.
    // Order A (dict order): inputs, m0,b0,t0, m1,b1,t1, m2,b2,t2, m3,b3,t3, m4,b4
    // Order B (signature):  inputs, m0..m4, b0..b4, t0..t3
    int im[5], ib[5], it[4];
    if (n_in >= 15 && in_sizes[2] == in_sizes[1]) {
        im[0] = 1;  ib[0] = 2;  it[0] = 3;
        im[1] = 4;  ib[1] = 5;  it[1] = 6;
        im[2] = 7;  ib[2] = 8;  it[2] = 9;
        im[3] = 10; ib[3] = 11; it[3] = 12;
        im[4] = 13; ib[4] = 14;
    } else {
        im[0] = 1; im[1] = 2; im[2] = 3; im[3] = 4; im[4] = 5;
        ib[0] = 6; ib[1] = 7; ib[2] = 8; ib[3] = 9; ib[4] = 10;
        it[0] = 11; it[1] = 12; it[2] = 13; it[3] = 14;
    }

    const float* in = (const float*)d_in[0];
    float* out = (float*)d_out;

    int C = in_sizes[ib[4]];          // b4 is (C,1,1)
    if (C <= 0 || C > 256) C = 192;
    int N = in_sizes[0] / C;
    long long CN = (long long)C * N;

    dim3 grid((N + EPB - 1) / EPB, C);
    eb_kernel<<<grid, 256>>>(
        in, out,
        (const float*)d_in[im[0]], (const float*)d_in[ib[0]], (const float*)d_in[it[0]],
        (const float*)d_in[im[1]], (const float*)d_in[ib[1]], (const float*)d_in[it[1]],
        (const float*)d_in[im[2]], (const float*)d_in[ib[2]], (const float*)d_in[it[2]],
        (const float*)d_in[im[3]], (const float*)d_in[ib[3]], (const float*)d_in[it[3]],
        (const float*)d_in[im[4]], (const float*)d_in[ib[4]],
        N, CN);
}